// round 14
// baseline (speedup 1.0000x reference)
#include <cuda_runtime.h>
#include <math.h>

// BayesRingRNN collapses exactly to a 2-scalar recurrence per batch:
// r_i(t) = u(t)*cos(phi_i) + v(t)*sin(phi_i)   (rank-2 weights, r0 in span).
//
// Kernel-level pipeline (graph-captured, two streams):
//   default stream: chain_slice x6  -- warp-per-batch serial recurrence,
//                   writes (u,v) into g_traj, state carried in g_state
//   side stream:    expand_slice x6 -- the R2-proven bandwidth kernel
//                   (occ 97%, 5.49 TB/s), gated per-slice by an event
// Chain slices (~6us) hide under expansions (~14us) -> makespan ~= C1 + sum(E).

#define NN 80
#define TT 1500
#define MAXB 1024
#define NS 6
#define SLICE (TT / NS)               // 250 steps per slice

__device__ float2 g_traj[(size_t)MAXB * TT];   // 12.3 MB (slice is L2-hot)
__device__ float2 g_state[MAXB];               // (u,v) carried between slices

// ---------------------------------------------------------- chain slice ---
__global__ void __launch_bounds__(128, 8)
chain_slice(const float* __restrict__ inputs,   // (B,T,2)
            const float* __restrict__ phi,      // (N,)
            float* __restrict__ out,            // tail: r_final (1,B,N)
            int B, float kz, int t0, long long out_size)
{
    const int b    = (blockIdx.x * blockDim.x + threadIdx.x) >> 5;
    const int lane = threadIdx.x & 31;
    if (b >= B) return;

    const float C1 = 0.01f / 3.0f;   // DT/(KP+KV)
    const float C3 = 2.0f / 3.0f;    // a_odd

    float u, v;
    if (t0 == 0) { u = 10.0f; v = 0.0f; }            // r0 = 10*cos(phi)
    else         { float2 st = g_state[b]; u = st.x; v = st.y; }

    const float2* __restrict__ inp =
        reinterpret_cast<const float2*>(inputs) + (size_t)b * TT;
    float2* __restrict__ tr = g_traj + (size_t)b * TT;

    const int tend = t0 + SLICE;
    float2 nx = inp[t0 + lane];      // prefetch first chunk (lane may overrun
                                     // chunk len; only lanes < len are used)
    for (int t = t0; t < tend; t += 32) {
        const int len = min(32, tend - t);
        const float2 x = nx;
        if (t + 32 + lane < tend) nx = inp[t + 32 + lane];

        float kc = 0.f, ks = 0.f, gi = 0.f;
        if (lane < len) {
            float s, co; sincosf(x.x, &s, &co);
            kc = kz * co; ks = kz * s; gi = C3 * x.y;
        }
        float su = u, sv = v;
        #pragma unroll 4
        for (int j = 0; j < len; ++j) {
            const float gij = __shfl_sync(0xffffffffu, gi, j);
            const float kcj = __shfl_sync(0xffffffffu, kc, j);
            const float ksj = __shfl_sync(0xffffffffu, ks, j);

            const float xx = fmaf(u, u, v * v);    // |z|^2 > 0 always
            const float y  = rsqrtf(xx);           // MUFU.RSQ
            const float d  = fmaf(-(C1 * xx), y, 1.0f);
            const float nu = fmaf(d, u, fmaf(-gij, v, kcj));
            const float nv = fmaf(d, v, fmaf( gij, u, ksj));
            u = nu; v = nv;
            if (j == lane) { su = u; sv = v; }
        }
        if (lane < len) tr[t + lane] = make_float2(su, sv);
    }

    if (lane == 0) g_state[b] = make_float2(u, v);

    // last slice also writes r_final (1,B,N) after the (B,T,N) block
    if (tend >= TT) {
        const long long base = (long long)B * TT * NN;
        if (out_size >= base + (long long)B * NN) {
            float* fp = out + base + (size_t)b * NN;
            float s, c;
            sincosf(phi[lane], &s, &c);        fp[lane]      = fmaf(v, s, u * c);
            sincosf(phi[lane + 32], &s, &c);   fp[lane + 32] = fmaf(v, s, u * c);
            if (lane < NN - 64) {
                sincosf(phi[lane + 64], &s, &c); fp[lane + 64] = fmaf(v, s, u * c);
            }
        }
    }
}

// --------------------------------------------------------- expand slice ---
// Byte-for-byte the R2 expansion (5.49 TB/s proven), restricted to a slice.
__global__ void __launch_bounds__(256)
expand_slice(const float* __restrict__ phi, float* __restrict__ out,
             int B, int t0)
{
    __shared__ float4 c4[NN / 4], s4[NN / 4];
    if (threadIdx.x < NN) {
        float s, c; sincosf(phi[threadIdx.x], &s, &c);
        reinterpret_cast<float*>(c4)[threadIdx.x] = c;
        reinterpret_cast<float*>(s4)[threadIdx.x] = s;
    }
    __syncthreads();

    float4* __restrict__ o4 = reinterpret_cast<float4*>(out);
    const int stride = gridDim.x * blockDim.x;
    const int total4 = B * SLICE * (NN / 4);

    for (int i = blockIdx.x * blockDim.x + threadIdx.x; i < total4; i += stride) {
        const int q   = i / (NN / 4);            // mul-shift
        const int n4  = i - q * (NN / 4);
        const int b   = q / SLICE;               // mul-shift (SLICE literal)
        const int tl  = q - b * SLICE;
        const int bt  = b * TT + t0 + tl;
        const float2 uv = g_traj[bt];            // L2-hot (just written)
        const float4 c = c4[n4];
        const float4 s = s4[n4];
        float4 o;
        o.x = fmaf(uv.y, s.x, uv.x * c.x);
        o.y = fmaf(uv.y, s.y, uv.x * c.y);
        o.z = fmaf(uv.y, s.z, uv.x * c.z);
        o.w = fmaf(uv.y, s.w, uv.x * c.w);
        o4[bt * (NN / 4) + n4] = o;
    }
}

// --- host-side exact replica of the reference's _xi_inv (double precision) --
static double xi_f(double a, double target)
{
    const double x = (a / 2.0) * (a / 2.0);
    double t0 = 1.0, t1 = a / 2.0;
    double i0 = t0, i1 = t1;
    for (int k = 1; k < 30; ++k) {
        t0 *= x / ((double)k * (double)k);
        t1 *= x / ((double)k * (double)(k + 1));
        i0 += t0;
        i1 += t1;
    }
    return a * i1 / i0 - target;
}

static float compute_kappa_z()
{
    const double target = 15.0 * 0.01;
    double lo = 1e-3, hi = 50.0;
    for (int i = 0; i < 200; ++i) {
        const double mid = 0.5 * (lo + hi);
        if (xi_f(lo, target) * xi_f(mid, target) <= 0.0) hi = mid;
        else lo = mid;
    }
    return (float)(0.5 * (lo + hi));
}

extern "C" void kernel_launch(void* const* d_in, const int* in_sizes, int n_in,
                              void* d_out, int out_size)
{
    const float* inputs = (const float*)d_in[0];  // (B,T,2)
    const float* phi    = (const float*)d_in[4];  // (N,)
    float* out = (float*)d_out;

    int B = in_sizes[0] / (2 * TT);
    if (B > MAXB) B = MAXB;
    const float kz = compute_kappa_z();

    // side stream + events (host-side resource creation: capture-legal,
    // kernel_launch is only invoked a handful of times so no buildup)
    cudaStream_t s2;
    cudaStreamCreateWithFlags(&s2, cudaStreamNonBlocking);
    cudaEvent_t evC[NS], evFin;
    for (int k = 0; k < NS; ++k)
        cudaEventCreateWithFlags(&evC[k], cudaEventDisableTiming);
    cudaEventCreateWithFlags(&evFin, cudaEventDisableTiming);

    const int cblocks = (B * 32 + 127) / 128;     // warp-per-batch

    for (int k = 0; k < NS; ++k) {
        chain_slice<<<cblocks, 128>>>(inputs, phi, out, B, kz, k * SLICE,
                                      (long long)out_size);
        cudaEventRecord(evC[k], 0);
        cudaStreamWaitEvent(s2, evC[k], 0);
        expand_slice<<<1184, 256, 0, s2>>>(phi, out, B, k * SLICE);
    }

    // join the side stream back into the default (captured) stream
    cudaEventRecord(evFin, s2);
    cudaStreamWaitEvent(0, evFin, 0);
}